// round 8
// baseline (speedup 1.0000x reference)
#include <cuda_runtime.h>
#include <cuda_bf16.h>
#include <cstdint>

// Problem constants (fixed by the reference setup)
#define N_NODES   128
#define M_PAR     2
#define CAL_N     256
#define N_OBS     64
#define SPB       128    // samples per block in main kernel
#define PF        32     // main-kernel noise prefetch depth (register ring)
#define PFP       8      // pilot-kernel prefetch depth

// Device scratch (allocation-free rule: __device__ globals)
__device__ float    g_pilot[N_NODES * CAL_N];
__device__ float4   g_cA[N_NODES];    // {w0, w1, b, sigma}  (root: {0,0,0,1})
__device__ uint32_t g_cPk[N_NODES];   // (p0*SPB*4) | ((p1*SPB*4) << 16), UNSIGNED:
                                      // p1*512 can be 0xFE00 -> bit31 set after <<16;
                                      // signed >>16 sign-extends to a negative smem
                                      // offset (the R4/R7 illegal-access bug).
__device__ int      g_root[N_NODES];  // 1 if root

// ---------------------------------------------------------------------------
// K1: pilot pass. 1 block, 256 threads (one per calibration sample).
// Branch-free: v = root ? root_pilot : relu(w.pv + b), root_pilot streamed
// through a register ring so the only serial dependency is the LDS chain.
// Parent indices packed as RAW 8-bit ids; shifted to byte offsets in-loop.
// ---------------------------------------------------------------------------
__global__ void __launch_bounds__(CAL_N)
pilot_kernel(const float* __restrict__ W,
             const float* __restrict__ b,
             const float* __restrict__ pm,
             const int*   __restrict__ pidx,
             const float* __restrict__ root_pilot)
{
    extern __shared__ float xs[];          // [N_NODES][CAL_N] = 128 KB
    __shared__ float4 pc[N_NODES];         // {w0, w1, b, rootFlag}
    __shared__ int    pp[N_NODES];         // p0 | (p1 << 8), raw indices

    int t = threadIdx.x;
    if (t < N_NODES) {
        float m0 = pm[t * 2 + 0], m1 = pm[t * 2 + 1];
        bool  root = (m0 == 0.f) && (m1 == 0.f);
        pc[t] = make_float4(W[t * 2 + 0] * m0, W[t * 2 + 1] * m1,
                            b[t], root ? 1.f : 0.f);
        pp[t] = (pidx[t * 2 + 0] & 0xff) | ((pidx[t * 2 + 1] & 0xff) << 8);
    }
    __syncthreads();

    char* myCol = reinterpret_cast<char*>(xs) + t * 4;

    float rp[PFP];
    #pragma unroll
    for (int j = 0; j < PFP; j++) rp[j] = __ldg(root_pilot + j * CAL_N + t);

    #pragma unroll 8
    for (int i = 0; i < N_NODES; i++) {
        float cur = rp[i & (PFP - 1)];
        int   ip  = i + PFP;
        if (ip < N_NODES) rp[i & (PFP - 1)] = __ldg(root_pilot + ip * CAL_N + t);

        float4 c  = pc[i];
        uint32_t pk = (uint32_t)pp[i];
        uint32_t o0 = (pk & 0xffu) << 10;          // *CAL_N*4 = *1024 bytes
        uint32_t o1 = ((pk >> 8) & 0xffu) << 10;
        float pv0 = *reinterpret_cast<float*>(myCol + o0);
        float pv1 = *reinterpret_cast<float*>(myCol + o1);
        float h   = fmaxf(fmaf(c.x, pv0, fmaf(c.y, pv1, c.z)), 0.f);
        float v   = (c.w != 0.f) ? cur : h;     // selp, uniform predicate
        *reinterpret_cast<float*>(myCol + i * (CAL_N * 4)) = v;
        g_pilot[i * CAL_N + t] = v;
    }
}

// ---------------------------------------------------------------------------
// K2: per-node sigma via exact order statistics (stable rank counting),
// plus per-node constant baking. 128 blocks x 256 threads.
// jnp.quantile linear: q25 at 63.75 -> v[63]+0.75*(v[64]-v[63]),
//                      q75 at 191.25 -> v[191]+0.25*(v[192]-v[191]).
// ---------------------------------------------------------------------------
__global__ void sigma_kernel(const float* __restrict__ W,
                             const float* __restrict__ b,
                             const float* __restrict__ pm,
                             const int*   __restrict__ pidx)
{
    __shared__ float v[CAL_N];
    __shared__ float q[4];
    int node = blockIdx.x;
    int t = threadIdx.x;
    float my = g_pilot[node * CAL_N + t];
    v[t] = my;
    __syncthreads();

    int rank = 0;
    #pragma unroll 8
    for (int j = 0; j < CAL_N; j++) {
        float o = v[j];                            // broadcast read
        rank += (o < my) || (o == my && j < t);    // stable rank: bijection 0..255
    }
    if (rank == 63)  q[0] = my;
    if (rank == 64)  q[1] = my;
    if (rank == 191) q[2] = my;
    if (rank == 192) q[3] = my;
    __syncthreads();

    if (t == 0) {
        float q25 = q[0] + 0.75f * (q[1] - q[0]);
        float q75 = q[2] + 0.25f * (q[3] - q[2]);
        float sig = 0.1f * fmaxf(q75 - q25, 1e-6f);

        float m0 = pm[node * 2 + 0], m1 = pm[node * 2 + 1];
        bool  root = (m0 == 0.f) && (m1 == 0.f);
        // Byte offsets for main kernel: p*SPB*4 = p*512, max 65024 (fits u16)
        uint32_t p0 = (uint32_t)(pidx[node * 2 + 0] & 0xff) * (SPB * 4);
        uint32_t p1 = (uint32_t)(pidx[node * 2 + 1] & 0xff) * (SPB * 4);
        if (root) {
            g_cA[node]   = make_float4(0.f, 0.f, 0.f, 1.f);
            g_cPk[node]  = 0u;
            g_root[node] = 1;
        } else {
            g_cA[node]   = make_float4(W[node * 2 + 0] * m0,
                                       W[node * 2 + 1] * m1,
                                       b[node], sig);
            g_cPk[node]  = p0 | (p1 << 16);       // unsigned: high half may set bit31
            g_root[node] = 0;
        }
    }
}

// ---------------------------------------------------------------------------
// K3: main pass. One sample per thread; node values in shared [node][tid]
// (conflict-free thread-private columns -> zero syncs in the loop).
// Per-node source pointers (root -> root_main row, else z_noise row) are baked
// into a uniform smem table, so the inner loop is:
//   LDS.64 base + 64b add + LDG (32-deep ring) + 2 imm-offset LDS + 3 FFMA + STS
// Ring depth 32 x ~15cyc/iter covers the DRAM latency; 12 warps/SM x 32 x 128B
// = 49KB outstanding per SM -> BW-bound streaming.
// ---------------------------------------------------------------------------
__global__ void __launch_bounds__(SPB)
main_kernel(const float* __restrict__ rm,
            const float* __restrict__ zn,
            const int*   __restrict__ chosen,
            float*       __restrict__ out,
            int n)
{
    extern __shared__ float shv[];                 // [N_NODES][SPB] = 64 KB
    __shared__ float4       cA[N_NODES];
    __shared__ uint32_t     cPk[N_NODES];
    __shared__ const float* baseP[N_NODES];        // uniform per-node source row
    __shared__ int          ch[N_OBS];

    int t = threadIdx.x;
    cA[t]  = g_cA[t];
    cPk[t] = g_cPk[t];
    baseP[t] = (g_root[t] ? rm : zn) + (size_t)t * n;
    if (t < N_OBS) ch[t] = chosen[t];
    __syncthreads();

    int s = blockIdx.x * SPB + t;
    if (s < n) {
        char* myCol = reinterpret_cast<char*>(shv) + t * 4;

        // Prime the prefetch ring
        float nz[PF];
        #pragma unroll
        for (int j = 0; j < PF; j++) nz[j] = __ldg(baseP[j] + s);

        #pragma unroll 32
        for (int i = 0; i < N_NODES; i++) {
            float cur = nz[i & (PF - 1)];
            int   ip  = i + PF;
            if (ip < N_NODES) nz[i & (PF - 1)] = __ldg(baseP[ip] + s);

            float4   c  = cA[i];                   // uniform LDS.128 broadcast
            uint32_t pk = cPk[i];
            float pv0 = *reinterpret_cast<float*>(myCol + (pk & 0xffffu));
            float pv1 = *reinterpret_cast<float*>(myCol + (pk >> 16));   // logical shift
            float h   = fmaxf(fmaf(c.x, pv0, fmaf(c.y, pv1, c.z)), 0.f);
            *reinterpret_cast<float*>(myCol + i * (SPB * 4)) = fmaf(c.w, cur, h);
        }

        // Gather chosen nodes, write transposed output row [s][0..63] as float4s
        float4* out4 = reinterpret_cast<float4*>(out + (size_t)s * N_OBS);
        #pragma unroll
        for (int j = 0; j < N_OBS / 4; j++) {
            int c0 = ch[4 * j + 0], c1 = ch[4 * j + 1];
            int c2 = ch[4 * j + 2], c3 = ch[4 * j + 3];
            out4[j] = make_float4(shv[c0 * SPB + t], shv[c1 * SPB + t],
                                  shv[c2 * SPB + t], shv[c3 * SPB + t]);
        }
    }
}

// ---------------------------------------------------------------------------
// Launch. Input order per setup_inputs dict:
// 0:n_samples 1:W 2:b 3:root_pilot 4:root_main 5:z_noise
// 6:par_mask 7:par_idx 8:is_root 9:chosen
// ---------------------------------------------------------------------------
extern "C" void kernel_launch(void* const* d_in, const int* in_sizes, int n_in,
                              void* d_out, int out_size)
{
    const float* W    = (const float*)d_in[1];
    const float* b    = (const float*)d_in[2];
    const float* rpil = (const float*)d_in[3];
    const float* rm   = (const float*)d_in[4];
    const float* zn   = (const float*)d_in[5];
    const float* pmsk = (const float*)d_in[6];
    const int*   pidx = (const int*)d_in[7];
    const int*   chos = (const int*)d_in[9];
    float*       out  = (float*)d_out;

    int n = in_sizes[4] / N_NODES;     // 262144

    cudaFuncSetAttribute(pilot_kernel,
                         cudaFuncAttributeMaxDynamicSharedMemorySize,
                         N_NODES * CAL_N * sizeof(float));
    cudaFuncSetAttribute(main_kernel,
                         cudaFuncAttributeMaxDynamicSharedMemorySize,
                         N_NODES * SPB * sizeof(float));

    pilot_kernel<<<1, CAL_N, N_NODES * CAL_N * sizeof(float)>>>(W, b, pmsk, pidx, rpil);
    sigma_kernel<<<N_NODES, CAL_N>>>(W, b, pmsk, pidx);

    int grid = (n + SPB - 1) / SPB;    // 2048
    main_kernel<<<grid, SPB, N_NODES * SPB * sizeof(float)>>>(rm, zn, chos, out, n);
}